// round 13
// baseline (speedup 1.0000x reference)
#include <cuda_runtime.h>
#include <cuda_bf16.h>
#include <math.h>
#include <stdint.h>

#define Bb 16
#define Cc 32
#define Hh 128
#define Ww 128
#define HW 16384
#define Rr 8
#define OUTC 32

typedef unsigned long long ull;

// ---------------- scratch (device globals; no allocation) ----------------
__device__ __align__(16) float d_kern[Bb * Rr * 288 * 32];   // [b][r][c*9+kl][oo]
__device__ float          d_pool[Bb * Cc * 9];               // [b][c][kl]
__device__ float          d_gate[Bb * 576];                  // [b][rr*9+kl]
__device__ unsigned char  d_sel[Bb * HW];                    // r1 | r2<<3
__device__ int            d_segcnt[Bb * Rr * 64];
__device__ int            d_segbase[Bb * Rr * 64];
__device__ int            d_cnt[Bb * Rr];
__device__ unsigned short d_list[Bb * Rr * HW];              // pix | flags<<14 (sorted by pix)
__device__ __align__(16) float d_cat[(size_t)Bb * HW * 64];  // PIXEL-MAJOR [b][pix][ch]
__device__ __align__(16) unsigned short d_wfbh[9 * 32 * 64]; // bf16 hi [tap][oo][ch]
__device__ __align__(16) unsigned short d_wfbl[9 * 32 * 64]; // bf16 lo [tap][oo][ch]

// ---------------- helpers ----------------
__device__ __forceinline__ uint32_t prmt7632(uint32_t a, uint32_t b) {
    uint32_t r; asm("prmt.b32 %0, %1, %2, 0x7632;" : "=r"(r) : "r"(a), "r"(b)); return r;
}
__device__ __forceinline__ uint32_t smem_u32(const void* p) {
    uint32_t a;
    asm("{ .reg .u64 t; cvta.to.shared.u64 t, %1; cvt.u32.u64 %0, t; }" : "=r"(a) : "l"(p));
    return a;
}
#define LDSM4(r0, r1, r2, r3, addr) \
    asm volatile("ldmatrix.sync.aligned.m8n8.x4.shared.b16 {%0,%1,%2,%3}, [%4];" \
                 : "=r"(r0), "=r"(r1), "=r"(r2), "=r"(r3) : "r"(addr))
#define MMA16816(c, a0, a1, a2, a3, b0, b1) \
    asm volatile("mma.sync.aligned.m16n8k16.row.col.f32.bf16.bf16.f32 " \
                 "{%0,%1,%2,%3},{%4,%5,%6,%7},{%8,%9},{%0,%1,%2,%3};" \
                 : "+f"((c)[0]), "+f"((c)[1]), "+f"((c)[2]), "+f"((c)[3]) \
                 : "r"(a0), "r"(a1), "r"(a2), "r"(a3), "r"(b0), "r"(b1))

// split v into bf16 hi (truncate) + bf16 lo(round)
__device__ __forceinline__ void split2(float v0, float v1, uint32_t& hi, uint32_t& lo) {
    hi = prmt7632(__float_as_uint(v0), __float_as_uint(v1));
    float l0 = v0 - __uint_as_float(__float_as_uint(v0) & 0xFFFF0000u);
    float l1 = v1 - __uint_as_float(__float_as_uint(v1) & 0xFFFF0000u);
    __nv_bfloat162 p = __floats2bfloat162_rn(l0, l1);
    lo = *reinterpret_cast<uint32_t*>(&p);
}

// ================= L1: pool (2 images/block) | s1 select | wf bf16-split =================
#define L1_POOL 256
#define L1_S1   1024
#define L1_WFT  72

__global__ void __launch_bounds__(256) l1_kernel(
    const float* __restrict__ in, const float* __restrict__ guide,
    const float* __restrict__ w_spa, const float* __restrict__ b_spa,
    const float* __restrict__ w_spec, const float* __restrict__ b_spec,
    const float* __restrict__ w_f) {
    int blk = blockIdx.x, t = threadIdx.x;
    __shared__ float srow[2][3][128];
    __shared__ int scnt[Rr];

    if (blk < L1_POOL) {
        int half = t >> 7, x = t & 127;
        int bc = blk * 2 + half;
        const float* img = in + (size_t)bc * HW;
        float rb0 = 0.f, rb1 = 0.f, rb2 = 0.f;
        #pragma unroll 4
        for (int yy = 0; yy < Hh; yy++) {
            float v = __ldg(img + yy * Ww + x);
            if (yy < 43) rb0 += v;
            if (yy >= 42 && yy < 86) rb1 += v;
            if (yy >= 85) rb2 += v;
        }
        srow[half][0][x] = rb0; srow[half][1][x] = rb1; srow[half][2][x] = rb2;
        __syncthreads();
        if (t < 18) {
            int h2 = t / 9, k = t % 9;
            int i = k / 3, j = k % 3;
            const int s[3] = {0, 42, 85}, e[3] = {43, 86, 128};
            const int span[3] = {43, 44, 43};
            float ssum = 0.f;
            for (int xx = s[j]; xx < e[j]; xx++) ssum += srow[h2][i][xx];
            d_pool[(blk * 2 + h2) * 9 + k] = ssum / (float)(span[i] * span[j]);
        }
    } else if (blk < L1_POOL + L1_S1) {
        int sb = blk - L1_POOL;
        int seg = sb & 63, b = sb >> 6;
        int pix = seg * 256 + t;

        float gv[Cc];
        #pragma unroll
        for (int c = 0; c < Cc; c++)
            gv[c] = __ldg(guide + ((size_t)(b * Cc + c)) * HW + pix);

        float best1 = -1e30f, best2 = -1e30f;
        int r1 = 0, r2 = 0;
        for (int r = 0; r < Rr; r++) {
            float s1 = __ldg(b_spa + r), s2 = __ldg(b_spec + r);
            #pragma unroll
            for (int c = 0; c < Cc; c++) {
                s1 += gv[c] * __ldg(w_spa + r * Cc + c);
                s2 += gv[c] * __ldg(w_spec + r * Cc + c);
            }
            if (s1 > best1) { best1 = s1; r1 = r; }
            if (s2 > best2) { best2 = s2; r2 = r; }
        }
        d_sel[b * HW + pix] = (unsigned char)(r1 | (r2 << 3));

        if (t < Rr) scnt[t] = 0;
        __syncthreads();
        if (r1 == r2) atomicAdd(&scnt[r1], 1);
        else { atomicAdd(&scnt[r1], 1); atomicAdd(&scnt[r2], 1); }
        __syncthreads();
        if (t < Rr) d_segcnt[(b * Rr + t) * 64 + seg] = scnt[t];
    } else {
        int idx = (blk - L1_POOL - L1_S1) * 256 + t;
        int ch = idx & 63, o = (idx >> 6) & 31, tap = idx >> 11;
        float v = w_f[(o * 64 + ch) * 9 + tap];
        uint32_t uv = __float_as_uint(v);
        uint32_t hv = uv & 0xFFFF0000u;
        float lo = v - __uint_as_float(hv);
        d_wfbh[idx] = (unsigned short)(hv >> 16);
        __nv_bfloat16 lb = __float2bfloat16(lo);
        d_wfbl[idx] = *reinterpret_cast<unsigned short*>(&lb);
    }
}

// ================= L2: gate (16 blocks) | s2 scan (1 block) =================
__global__ void __launch_bounds__(256) l2_kernel(
    const float* __restrict__ w1, const float* __restrict__ b1) {
    int blk = blockIdx.x, t = threadIdx.x;
    if (blk < Bb) {
        int b = blk;
        for (int i = t; i < 576; i += 256) {
            int rr = i / 9, kl = i % 9;
            float s = __ldg(b1 + rr);
            #pragma unroll
            for (int c = 0; c < Cc; c++)
                s += d_pool[(b * Cc + c) * 9 + kl] * __ldg(w1 + rr * Cc + c);
            d_gate[b * 576 + i] = 1.f / (1.f + expf(-s));
        }
    } else {
        if (t < Bb * Rr) {
            int s = 0;
            for (int seg = 0; seg < 64; seg++) {
                d_segbase[t * 64 + seg] = s;
                s += d_segcnt[t * 64 + seg];
            }
            d_cnt[t] = s;
        }
    }
}

// ================= L3: kern gen (4608 blocks) | s3 emit (1024 blocks) =================
#define L3_KERN 4608

__global__ void __launch_bounds__(256) l3_kernel(
    const float* __restrict__ w2, const float* __restrict__ b2) {
    int blk = blockIdx.x, t = threadIdx.x;
    __shared__ int wcnt[8][8];

    if (blk < L3_KERN) {
        int idx = blk * 256 + t;
        int oo = idx & 31;
        int ckl = (idx >> 5) % 288;
        int t2 = idx / (288 * 32);
        int r = t2 & 7;
        int b = t2 >> 3;
        int c = ckl / 9, kl = ckl % 9;
        int jj = r * 1024 + oo * 32 + c;
        float v = __ldg(b2 + jj);
        float4 wa = __ldg((const float4*)(w2 + jj * 8));
        float4 wb = __ldg((const float4*)(w2 + jj * 8 + 4));
        const float* gb = d_gate + b * 576 + r * 72 + kl;
        v += gb[0]  * wa.x + gb[9]  * wa.y + gb[18] * wa.z + gb[27] * wa.w;
        v += gb[36] * wb.x + gb[45] * wb.y + gb[54] * wb.z + gb[63] * wb.w;
        d_kern[idx] = v;
    } else {
        int sb = blk - L3_KERN;
        int seg = sb & 63, b = sb >> 6;
        int w = t >> 5, lane = t & 31;
        int pix = seg * 256 + t;
        int sel = d_sel[b * HW + pix];
        int r1 = sel & 7, r2 = sel >> 3;

        int rank1 = 0, rank2 = 0;
        unsigned ltm = (1u << lane) - 1u;
        #pragma unroll
        for (int r = 0; r < Rr; r++) {
            unsigned m = __ballot_sync(0xFFFFFFFFu, (r1 == r) || (r2 == r));
            if (lane == 0) wcnt[w][r] = __popc(m);
            if (r1 == r) rank1 = __popc(m & ltm);
            if (r2 == r) rank2 = __popc(m & ltm);
        }
        __syncthreads();
        int wb1 = 0, wb2 = 0;
        for (int w2i = 0; w2i < w; w2i++) { wb1 += wcnt[w2i][r1]; wb2 += wcnt[w2i][r2]; }

        unsigned short pv = (unsigned short)pix;
        if (r1 == r2) {
            int off = d_segbase[(b * Rr + r1) * 64 + seg] + wb1 + rank1;
            d_list[(b * Rr + r1) * HW + off] = (unsigned short)(pv | (3u << 14));
        } else {
            int off1 = d_segbase[(b * Rr + r1) * 64 + seg] + wb1 + rank1;
            d_list[(b * Rr + r1) * HW + off1] = (unsigned short)(pv | (1u << 14));
            int off2 = d_segbase[(b * Rr + r2) * 64 + seg] + wb2 + rank2;
            d_list[(b * Rr + r2) * HW + off2] = (unsigned short)(pv | (2u << 14));
        }
    }
}

// ================= L4: dynconv via mma.sync — M=128 entries, N=32, K=288 (+pad) =================
// K split: 5 chunks of 64 (2 taps x 32 ch; tap 9 zero-padded via zero B).
// smem: A hi/lo [128][64] bf16 (16KB each), B hi/lo [5][32][64] bf16 (20KB each), meta 1KB.
#define DA_BYTES 16384
#define DB_BYTES 20480
#define D_SMEM (2 * DA_BYTES + 2 * DB_BYTES + 1024)   // 75776

__global__ void __launch_bounds__(256) dynconv_mma_kernel(const float* __restrict__ in) {
    int b = blockIdx.z, r = blockIdx.y;
    int cnt = d_cnt[b * Rr + r];
    int base = blockIdx.x * 128;
    if (base >= cnt) return;

    extern __shared__ __align__(16) char sm[];
    char* Ah = sm;
    char* Al = sm + DA_BYTES;
    char* Bh = sm + 2 * DA_BYTES;
    char* Bl = sm + 2 * DA_BYTES + DB_BYTES;
    int* s_pix = (int*)(sm + 2 * DA_BYTES + 2 * DB_BYTES);
    int* s_fl  = s_pix + 128;
    uint32_t AhA = smem_u32(Ah), AlA = smem_u32(Al);
    uint32_t BhA = smem_u32(Bh), BlA = smem_u32(Bl);

    int tid = threadIdx.x, wid = tid >> 5, l = tid & 31;

    // ---- meta ----
    const unsigned short* lst = d_list + (b * Rr + r) * HW;
    if (tid < 128) {
        int e = base + tid;
        int ent = (e < cnt) ? (int)lst[e] : 0;
        s_fl[tid] = (e < cnt) ? (ent >> 14) : 0;
        s_pix[tid] = ent & 0x3FFF;
    }

    // ---- stage B: all 5 chunks, [n][k=tp*32+c], swizzled pitch-128 rows ----
    {
        const float* kern = d_kern + (size_t)(b * Rr + r) * 9216;
        #pragma unroll
        for (int i = 0; i < 20; i++) {
            int idx = i * 256 + tid;        // pair index 0..5119
            int chunk = idx >> 10;
            int rem = idx & 1023;
            int n = rem >> 5, k = (rem & 31) * 2;
            int tp = k >> 5;
            int tap = chunk * 2 + tp;
            int c = k & 31;
            float v0 = 0.f, v1 = 0.f;
            if (tap < 9) {
                v0 = __ldg(kern + (c * 9 + tap) * 32 + n);
                v1 = __ldg(kern + ((c + 1) * 9 + tap) * 32 + n);
            }
            uint32_t hi, lo;
            split2(v0, v1, hi, lo);
            int u = (k >> 3) & 7;
            uint32_t off = chunk * 4096 + n * 128 + ((u ^ (n & 7)) << 4) + (k & 7) * 2;
            *(uint32_t*)(Bh + off) = hi;
            *(uint32_t*)(Bl + off) = lo;
        }
    }
    __syncthreads();

    // ---- per-thread entry meta ----
    int e = tid & 127;
    int h7 = tid >> 7;
    int mypix = s_pix[e], myfl = s_fl[e];
    int my_y = mypix >> 7, my_x = mypix & 127;
    const float* inb = in + (size_t)b * Cc * HW + mypix;

    float acc[4][4];
    #pragma unroll
    for (int nt = 0; nt < 4; nt++)
        #pragma unroll
        for (int i = 0; i < 4; i++) acc[nt][i] = 0.f;

    int rra = wid * 16 + (l & 15);
    int kha = l >> 4;
    int nn = ((l >> 4) & 1) * 8 + (l & 7);
    int khb = (l >> 3) & 1;

    #pragma unroll
    for (int chunk = 0; chunk < 5; chunk++) {
        // ---- stage A for this chunk: thread owns entry e, stages channels cp = i*2+h7 ----
        #pragma unroll
        for (int tp = 0; tp < 2; tp++) {
            const int tap = chunk * 2 + tp;
            if (tap < 9) {
                const int ky = tap / 3, kx = tap % 3;
                bool tv = myfl && ((unsigned)(my_y + ky - 1) < 128u) &&
                          ((unsigned)(my_x + kx - 1) < 128u);
                const float* ip = inb + (ky - 1) * Ww + (kx - 1);
                #pragma unroll
                for (int i = 0; i < 8; i++) {
                    int cp = i * 2 + h7;          // 0..15
                    int c = cp * 2;
                    float v0 = tv ? __ldg(ip + (size_t)c * HW) : 0.f;
                    float v1 = tv ? __ldg(ip + (size_t)(c + 1) * HW) : 0.f;
                    uint32_t hi, lo;
                    split2(v0, v1, hi, lo);
                    int k = tp * 32 + c;
                    int u = k >> 3;
                    uint32_t off = e * 128 + ((u ^ (e & 7)) << 4) + (k & 7) * 2;
                    *(uint32_t*)(Ah + off) = hi;
                    *(uint32_t*)(Al + off) = lo;
                }
            }
        }
        __syncthreads();

        // ---- mma over this chunk (k64 = 4 ksteps) ----
        #pragma unroll
        for (int kc = 0; kc < 4; kc++) {
            uint32_t ua = (uint32_t)(kc * 2 + kha);
            uint32_t aoff = rra * 128 + ((ua ^ (rra & 7)) << 4);
            uint32_t ah0, ah1, ah2, ah3, al0, al1, al2, al3;
            LDSM4(ah0, ah1, ah2, ah3, AhA + aoff);
            LDSM4(al0, al1, al2, al3, AlA + aoff);

            uint32_t ub = (uint32_t)(kc * 2 + khb);
            uint32_t boff1 = chunk * 4096 + nn * 128 + ((ub ^ (nn & 7)) << 4);
            uint32_t boff2 = chunk * 4096 + (nn + 16) * 128 + ((ub ^ ((nn + 16) & 7)) << 4);
            uint32_t bh0, bh1, bh2, bh3, bh4, bh5, bh6, bh7;
            uint32_t bl0, bl1, bl2, bl3, bl4, bl5, bl6, bl7;
            LDSM4(bh0, bh1, bh2, bh3, BhA + boff1);
            LDSM4(bh4, bh5, bh6, bh7, BhA + boff2);
            LDSM4(bl0, bl1, bl2, bl3, BlA + boff1);
            LDSM4(bl4, bl5, bl6, bl7, BlA + boff2);

            MMA16816(acc[0], ah0, ah1, ah2, ah3, bh0, bh1);
            MMA16816(acc[1], ah0, ah1, ah2, ah3, bh2, bh3);
            MMA16816(acc[2], ah0, ah1, ah2, ah3, bh4, bh5);
            MMA16816(acc[3], ah0, ah1, ah2, ah3, bh6, bh7);
            MMA16816(acc[0], ah0, ah1, ah2, ah3, bl0, bl1);
            MMA16816(acc[1], ah0, ah1, ah2, ah3, bl2, bl3);
            MMA16816(acc[2], ah0, ah1, ah2, ah3, bl4, bl5);
            MMA16816(acc[3], ah0, ah1, ah2, ah3, bl6, bl7);
            MMA16816(acc[0], al0, al1, al2, al3, bh0, bh1);
            MMA16816(acc[1], al0, al1, al2, al3, bh2, bh3);
            MMA16816(acc[2], al0, al1, al2, al3, bh4, bh5);
            MMA16816(acc[3], al0, al1, al2, al3, bh6, bh7);
        }
        __syncthreads();   // before next chunk restages A
    }

    // ---- epilogue: D frags -> d_cat[pix][ch], gated by flags ----
    int g = l >> 2, tq = l & 3;
    float* catb = d_cat + (size_t)b * HW * 64;
    #pragma unroll
    for (int rr2 = 0; rr2 < 2; rr2++) {
        int er = wid * 16 + g + rr2 * 8;
        int p = s_pix[er], f = s_fl[er];
        float* cp0 = catb + (size_t)p * 64 + tq * 2;
        #pragma unroll
        for (int nt = 0; nt < 4; nt++) {
            float2 v = make_float2(acc[nt][rr2 * 2], acc[nt][rr2 * 2 + 1]);
            if (f & 1) *(float2*)(cp0 + nt * 8) = v;
            if (f & 2) *(float2*)(cp0 + 32 + nt * 8) = v;
        }
    }
}

// ================= L5: fusion via mma.sync bf16 (3-product split) — unchanged =================
#define FA_BYTES 16640
#define FB_BYTES 4096
#define F_SMEM (2 * FA_BYTES + 2 * FB_BYTES)   // 41472

__global__ void __launch_bounds__(256) fusion_mma_kernel(
    const float* __restrict__ in, const float* __restrict__ b_f,
    float* __restrict__ out) {
    extern __shared__ __align__(16) char sm[];
    char* Ah = sm;
    char* Al = sm + FA_BYTES;
    char* Bh = sm + 2 * FA_BYTES;
    char* Bl = sm + 2 * FA_BYTES + FB_BYTES;
    uint32_t AhA = smem_u32(Ah), AlA = smem_u32(Al);
    uint32_t BhA = smem_u32(Bh), BlA = smem_u32(Bl);

    int tid = threadIdx.x, wid = tid >> 5, l = tid & 31;
    int g = l >> 2, tq = l & 3;
    int y = blockIdx.x, b = blockIdx.y;
    const float* catb = d_cat + (size_t)b * HW * 64;

    float acc[4][4];
    #pragma unroll
    for (int nt = 0; nt < 4; nt++)
        #pragma unroll
        for (int i = 0; i < 4; i++) acc[nt][i] = 0.f;

    for (int ky = 0; ky < 3; ky++) {
        int yy = y + ky - 1;
        if ((unsigned)yy >= 128u) continue;
        __syncthreads();
        {
            const float4* srcb = (const float4*)(catb + ((size_t)yy * 128 - 1) * 64);
            #pragma unroll
            for (int i = 0; i < 9; i++) {
                int f = i * 256 + tid;
                if (f < 2080) {
                    int rr = f >> 4, c4 = f & 15;
                    int sx = rr - 1;
                    float4 v = make_float4(0.f, 0.f, 0.f, 0.f);
                    if ((unsigned)sx < 128u) v = __ldg(srcb + f);
                    uint32_t hx = prmt7632(__float_as_uint(v.x), __float_as_uint(v.y));
                    uint32_t hz = prmt7632(__float_as_uint(v.z), __float_as_uint(v.w));
                    float lx = v.x - __uint_as_float(__float_as_uint(v.x) & 0xFFFF0000u);
                    float ly = v.y - __uint_as_float(__float_as_uint(v.y) & 0xFFFF0000u);
                    float lz = v.z - __uint_as_float(__float_as_uint(v.z) & 0xFFFF0000u);
                    float lw = v.w - __uint_as_float(__float_as_uint(v.w) & 0xFFFF0000u);
                    __nv_bfloat162 p0 = __floats2bfloat162_rn(lx, ly);
                    __nv_bfloat162 p1 = __floats2bfloat162_rn(lz, lw);
                    uint32_t off = rr * 128 + ((((c4 >> 1)) ^ (rr & 7)) << 4) + (c4 & 1) * 8;
                    *(uint2*)(Ah + off) = make_uint2(hx, hz);
                    *(uint2*)(Al + off) = make_uint2(*(uint32_t*)&p0, *(uint32_t*)&p1);
                }
            }
        }
        for (int kx = 0; kx < 3; kx++) {
            int tap = ky * 3 + kx;
            __syncthreads();
            {
                int oo = tid >> 3, u = tid & 7;
                uint4 sh = ((const uint4*)d_wfbh)[tap * 256 + tid];
                uint4 sl = ((const uint4*)d_wfbl)[tap * 256 + tid];
                uint32_t off = oo * 128 + ((u ^ (oo & 7)) << 4);
                *(uint4*)(Bh + off) = sh;
                *(uint4*)(Bl + off) = sl;
            }
            __syncthreads();

            int rra = wid * 16 + (l & 15) + kx;
            int kha = l >> 4;
            int nn = ((l >> 4) & 1) * 8 + (l & 7);
            int khb = (l >> 3) & 1;

            #pragma unroll
            for (int kc = 0; kc < 4; kc++) {
                uint32_t ua = (uint32_t)(kc * 2 + kha);
                uint32_t aoff = rra * 128 + ((ua ^ (rra & 7)) << 4);
                uint32_t ah0, ah1, ah2, ah3, al0, al1, al2, al3;
                LDSM4(ah0, ah1, ah2, ah3, AhA + aoff);
                LDSM4(al0, al1, al2, al3, AlA + aoff);

                uint32_t ub = (uint32_t)(kc * 2 + khb);
                uint32_t boff1 = nn * 128 + ((ub ^ (nn & 7)) << 4);
                uint32_t boff2 = (nn + 16) * 128 + ((ub ^ ((nn + 16) & 7)) << 4);
                uint32_t bh0, bh1, bh2, bh3, bh4, bh5, bh6, bh7;
                uint32_t bl0, bl1, bl2, bl3, bl4, bl5, bl6, bl7;
                LDSM4(bh0, bh1, bh2, bh3, BhA + boff1);
                LDSM4(bh4, bh5, bh6, bh7, BhA + boff2);
                LDSM4(bl0, bl1, bl2, bl3, BlA + boff1);
                LDSM4(bl4, bl5, bl6, bl7, BlA + boff2);

                MMA16816(acc[0], ah0, ah1, ah2, ah3, bh0, bh1);
                MMA16816(acc[1], ah0, ah1, ah2, ah3, bh2, bh3);
                MMA16816(acc[2], ah0, ah1, ah2, ah3, bh4, bh5);
                MMA16816(acc[3], ah0, ah1, ah2, ah3, bh6, bh7);
                MMA16816(acc[0], ah0, ah1, ah2, ah3, bl0, bl1);
                MMA16816(acc[1], ah0, ah1, ah2, ah3, bl2, bl3);
                MMA16816(acc[2], ah0, ah1, ah2, ah3, bl4, bl5);
                MMA16816(acc[3], ah0, ah1, ah2, ah3, bl6, bl7);
                MMA16816(acc[0], al0, al1, al2, al3, bh0, bh1);
                MMA16816(acc[1], al0, al1, al2, al3, bh2, bh3);
                MMA16816(acc[2], al0, al1, al2, al3, bh4, bh5);
                MMA16816(acc[3], al0, al1, al2, al3, bh6, bh7);
            }
        }
    }

    int px0 = wid * 16 + g;
    size_t rowoff = (size_t)y * Ww;
    #pragma unroll
    for (int nt = 0; nt < 4; nt++) {
        int o0 = nt * 8 + tq * 2;
        float bi0 = __ldg(b_f + o0), bi1 = __ldg(b_f + o0 + 1);
        size_t i00 = ((size_t)(b * OUTC + o0)) * HW + rowoff + px0;
        size_t i01 = ((size_t)(b * OUTC + o0 + 1)) * HW + rowoff + px0;
        out[i00]     = acc[nt][0] + bi0 + __ldg(in + i00);
        out[i01]     = acc[nt][1] + bi1 + __ldg(in + i01);
        out[i00 + 8] = acc[nt][2] + bi0 + __ldg(in + i00 + 8);
        out[i01 + 8] = acc[nt][3] + bi1 + __ldg(in + i01 + 8);
    }
}

// ---------------- launch ----------------
extern "C" void kernel_launch(void* const* d_in, const int* in_sizes, int n_in,
                              void* d_out, int out_size) {
    const float* input  = (const float*)d_in[0];
    const float* guide  = (const float*)d_in[1];
    const float* w1     = (const float*)d_in[2];
    const float* b1     = (const float*)d_in[3];
    const float* w2     = (const float*)d_in[4];
    const float* b2     = (const float*)d_in[5];
    const float* w_spa  = (const float*)d_in[6];
    const float* b_spa  = (const float*)d_in[7];
    const float* w_spec = (const float*)d_in[8];
    const float* b_spec = (const float*)d_in[9];
    const float* w_f    = (const float*)d_in[10];
    const float* b_f    = (const float*)d_in[11];
    float* out = (float*)d_out;

    cudaFuncSetAttribute(dynconv_mma_kernel, cudaFuncAttributeMaxDynamicSharedMemorySize, D_SMEM);

    l1_kernel<<<L1_POOL + L1_S1 + L1_WFT, 256>>>(input, guide, w_spa, b_spa, w_spec, b_spec, w_f);
    l2_kernel<<<Bb + 1, 256>>>(w1, b1);
    l3_kernel<<<L3_KERN + 1024, 256>>>(w2, b2);
    dynconv_mma_kernel<<<dim3(128, Rr, Bb), 256, D_SMEM>>>(input);
    fusion_mma_kernel<<<dim3(Hh, Bb), 256, F_SMEM>>>(input, b_f, out);
}

// round 14
// speedup vs baseline: 1.7375x; 1.7375x over previous
#include <cuda_runtime.h>
#include <cuda_bf16.h>
#include <math.h>
#include <stdint.h>

#define Bb 16
#define Cc 32
#define Hh 128
#define Ww 128
#define HW 16384
#define Rr 8
#define OUTC 32

typedef unsigned long long ull;

// ---------------- scratch (device globals; no allocation) ----------------
__device__ float          d_pool[Bb * Cc * 9];               // [b][c][kl]
__device__ float          d_gate[Bb * 576];                  // [b][rr*9+kl]
__device__ unsigned char  d_sel[Bb * HW];                    // r1 | r2<<3
__device__ int            d_segcnt[Bb * Rr * 64];
__device__ int            d_segbase[Bb * Rr * 64];
__device__ int            d_cnt[Bb * Rr];
__device__ unsigned short d_list[Bb * Rr * HW];              // pix | flags<<14 (sorted by pix)
__device__ __align__(16) float d_cat[(size_t)Bb * HW * 64];  // PIXEL-MAJOR [b][pix][ch]
__device__ __align__(16) unsigned short d_wfbh[9 * 32 * 64]; // bf16 hi [tap][oo][ch]
__device__ __align__(16) unsigned short d_wfbl[9 * 32 * 64]; // bf16 lo [tap][oo][ch]
__device__ __align__(16) unsigned short d_ibh[(size_t)Bb * HW * 32]; // input bf16 hi [b][pix][ch]
__device__ __align__(16) unsigned short d_ibl[(size_t)Bb * HW * 32]; // input bf16 lo
__device__ __align__(16) uint32_t d_kbh[Bb * Rr * 5 * 32 * 32]; // kern bf16-pair hi [b][r][chunk][n][k2]
__device__ __align__(16) uint32_t d_kbl[Bb * Rr * 5 * 32 * 32]; // kern bf16-pair lo

// ---------------- helpers ----------------
__device__ __forceinline__ uint32_t prmt7632(uint32_t a, uint32_t b) {
    uint32_t r; asm("prmt.b32 %0, %1, %2, 0x7632;" : "=r"(r) : "r"(a), "r"(b)); return r;
}
__device__ __forceinline__ uint32_t smem_u32(const void* p) {
    uint32_t a;
    asm("{ .reg .u64 t; cvta.to.shared.u64 t, %1; cvt.u32.u64 %0, t; }" : "=r"(a) : "l"(p));
    return a;
}
#define LDSM4(r0, r1, r2, r3, addr) \
    asm volatile("ldmatrix.sync.aligned.m8n8.x4.shared.b16 {%0,%1,%2,%3}, [%4];" \
                 : "=r"(r0), "=r"(r1), "=r"(r2), "=r"(r3) : "r"(addr))
#define MMA16816(c, a0, a1, a2, a3, b0, b1) \
    asm volatile("mma.sync.aligned.m16n8k16.row.col.f32.bf16.bf16.f32 " \
                 "{%0,%1,%2,%3},{%4,%5,%6,%7},{%8,%9},{%0,%1,%2,%3};" \
                 : "+f"((c)[0]), "+f"((c)[1]), "+f"((c)[2]), "+f"((c)[3]) \
                 : "r"(a0), "r"(a1), "r"(a2), "r"(a3), "r"(b0), "r"(b1))

// split (v0,v1) into packed bf16 hi (truncate) + bf16 lo (round of residue)
__device__ __forceinline__ void split2(float v0, float v1, uint32_t& hi, uint32_t& lo) {
    hi = prmt7632(__float_as_uint(v0), __float_as_uint(v1));
    float l0 = v0 - __uint_as_float(__float_as_uint(v0) & 0xFFFF0000u);
    float l1 = v1 - __uint_as_float(__float_as_uint(v1) & 0xFFFF0000u);
    __nv_bfloat162 p = __floats2bfloat162_rn(l0, l1);
    lo = *reinterpret_cast<uint32_t*>(&p);
}

// ================= L1: pool | s1 select | wf split | input transpose+split =================
#define L1_POOL 256
#define L1_S1   1024
#define L1_WFT  72
#define L1_TRANS 8192

__global__ void __launch_bounds__(256) l1_kernel(
    const float* __restrict__ in, const float* __restrict__ guide,
    const float* __restrict__ w_spa, const float* __restrict__ b_spa,
    const float* __restrict__ w_spec, const float* __restrict__ b_spec,
    const float* __restrict__ w_f) {
    int blk = blockIdx.x, t = threadIdx.x;
    __shared__ float srow[2][3][128];
    __shared__ int scnt[Rr];
    __shared__ float tt[32][33];

    if (blk < L1_POOL) {
        int half = t >> 7, x = t & 127;
        int bc = blk * 2 + half;
        const float* img = in + (size_t)bc * HW;
        float rb0 = 0.f, rb1 = 0.f, rb2 = 0.f;
        #pragma unroll 4
        for (int yy = 0; yy < Hh; yy++) {
            float v = __ldg(img + yy * Ww + x);
            if (yy < 43) rb0 += v;
            if (yy >= 42 && yy < 86) rb1 += v;
            if (yy >= 85) rb2 += v;
        }
        srow[half][0][x] = rb0; srow[half][1][x] = rb1; srow[half][2][x] = rb2;
        __syncthreads();
        if (t < 18) {
            int h2 = t / 9, k = t % 9;
            int i = k / 3, j = k % 3;
            const int s[3] = {0, 42, 85}, e[3] = {43, 86, 128};
            const int span[3] = {43, 44, 43};
            float ssum = 0.f;
            for (int xx = s[j]; xx < e[j]; xx++) ssum += srow[h2][i][xx];
            d_pool[(blk * 2 + h2) * 9 + k] = ssum / (float)(span[i] * span[j]);
        }
    } else if (blk < L1_POOL + L1_S1) {
        int sb = blk - L1_POOL;
        int seg = sb & 63, b = sb >> 6;
        int pix = seg * 256 + t;

        float gv[Cc];
        #pragma unroll
        for (int c = 0; c < Cc; c++)
            gv[c] = __ldg(guide + ((size_t)(b * Cc + c)) * HW + pix);

        float best1 = -1e30f, best2 = -1e30f;
        int r1 = 0, r2 = 0;
        for (int r = 0; r < Rr; r++) {
            float s1 = __ldg(b_spa + r), s2 = __ldg(b_spec + r);
            #pragma unroll
            for (int c = 0; c < Cc; c++) {
                s1 += gv[c] * __ldg(w_spa + r * Cc + c);
                s2 += gv[c] * __ldg(w_spec + r * Cc + c);
            }
            if (s1 > best1) { best1 = s1; r1 = r; }
            if (s2 > best2) { best2 = s2; r2 = r; }
        }
        d_sel[b * HW + pix] = (unsigned char)(r1 | (r2 << 3));

        if (t < Rr) scnt[t] = 0;
        __syncthreads();
        if (r1 == r2) atomicAdd(&scnt[r1], 1);
        else { atomicAdd(&scnt[r1], 1); atomicAdd(&scnt[r2], 1); }
        __syncthreads();
        if (t < Rr) d_segcnt[(b * Rr + t) * 64 + seg] = scnt[t];
    } else if (blk < L1_POOL + L1_S1 + L1_WFT) {
        int idx = (blk - L1_POOL - L1_S1) * 256 + t;
        int ch = idx & 63, o = (idx >> 6) & 31, tap = idx >> 11;
        float v = w_f[(o * 64 + ch) * 9 + tap];
        uint32_t uv = __float_as_uint(v);
        uint32_t hv = uv & 0xFFFF0000u;
        float lo = v - __uint_as_float(hv);
        d_wfbh[idx] = (unsigned short)(hv >> 16);
        __nv_bfloat16 lb = __float2bfloat16(lo);
        d_wfbl[idx] = *reinterpret_cast<unsigned short*>(&lb);
    } else {
        // ---- input transpose + bf16 split: d_ibh/d_ibl[b][pix][ch] ----
        int tb = blk - (L1_POOL + L1_S1 + L1_WFT);
        int px0 = (tb & 511) * 32;
        int b = tb >> 9;
        int lane = t & 31, wr = t >> 5;
        #pragma unroll
        for (int i = 0; i < 4; i++) {
            int c = wr + i * 8;
            tt[c][lane] = __ldg(in + ((size_t)(b * Cc + c)) * HW + px0 + lane);
        }
        __syncthreads();
        int lp = lane & 15;
        bool isLo = lane >= 16;
        #pragma unroll
        for (int i = 0; i < 4; i++) {
            int pr = wr + i * 8;
            float v0 = tt[2 * lp][pr], v1 = tt[2 * lp + 1][pr];
            uint32_t hi, lo;
            split2(v0, v1, hi, lo);
            size_t basei = ((size_t)b * HW + px0 + pr) * 32 + 2 * lp;
            if (!isLo) *(uint32_t*)(d_ibh + basei) = hi;
            else       *(uint32_t*)(d_ibl + basei) = lo;
        }
    }
}

// ================= L2: gate (16 blocks) | s2 scan (1 block) =================
__global__ void __launch_bounds__(256) l2_kernel(
    const float* __restrict__ w1, const float* __restrict__ b1) {
    int blk = blockIdx.x, t = threadIdx.x;
    if (blk < Bb) {
        int b = blk;
        for (int i = t; i < 576; i += 256) {
            int rr = i / 9, kl = i % 9;
            float s = __ldg(b1 + rr);
            #pragma unroll
            for (int c = 0; c < Cc; c++)
                s += d_pool[(b * Cc + c) * 9 + kl] * __ldg(w1 + rr * Cc + c);
            d_gate[b * 576 + i] = 1.f / (1.f + expf(-s));
        }
    } else {
        if (t < Bb * Rr) {
            int s = 0;
            for (int seg = 0; seg < 64; seg++) {
                d_segbase[t * 64 + seg] = s;
                s += d_segcnt[t * 64 + seg];
            }
            d_cnt[t] = s;
        }
    }
}

// ================= L3: kern gen -> bf16 GEMM layout (2560 blocks) | s3 emit (1024) =================
#define L3_KERN 2560

__global__ void __launch_bounds__(256) l3_kernel(
    const float* __restrict__ w2, const float* __restrict__ b2) {
    int blk = blockIdx.x, t = threadIdx.x;
    __shared__ int wcnt[8][8];

    if (blk < L3_KERN) {
        int idx = blk * 256 + t;
        int k2 = idx & 31;
        int n = (idx >> 5) & 31;
        int chunk = (idx >> 10) % 5;
        int t2 = idx / 5120;
        int r = t2 & 7, b = t2 >> 3;
        int k = k2 * 2;
        int tp = k >> 5, c = k & 31;
        int tap = chunk * 2 + tp;
        float v0 = 0.f, v1 = 0.f;
        if (tap < 9) {
            int jj = r * 1024 + n * 32 + c;
            const float* gb = d_gate + b * 576 + r * 72 + tap;
            v0 = __ldg(b2 + jj);
            v1 = __ldg(b2 + jj + 1);
            float4 wa = __ldg((const float4*)(w2 + jj * 8));
            float4 wb = __ldg((const float4*)(w2 + jj * 8 + 4));
            v0 += gb[0]  * wa.x + gb[9]  * wa.y + gb[18] * wa.z + gb[27] * wa.w;
            v0 += gb[36] * wb.x + gb[45] * wb.y + gb[54] * wb.z + gb[63] * wb.w;
            float4 wc = __ldg((const float4*)(w2 + (jj + 1) * 8));
            float4 wd = __ldg((const float4*)(w2 + (jj + 1) * 8 + 4));
            v1 += gb[0]  * wc.x + gb[9]  * wc.y + gb[18] * wc.z + gb[27] * wc.w;
            v1 += gb[36] * wd.x + gb[45] * wd.y + gb[54] * wd.z + gb[63] * wd.w;
        }
        uint32_t hi, lo;
        split2(v0, v1, hi, lo);
        d_kbh[idx] = hi;
        d_kbl[idx] = lo;
    } else {
        int sb = blk - L3_KERN;
        int seg = sb & 63, b = sb >> 6;
        int w = t >> 5, lane = t & 31;
        int pix = seg * 256 + t;
        int sel = d_sel[b * HW + pix];
        int r1 = sel & 7, r2 = sel >> 3;

        int rank1 = 0, rank2 = 0;
        unsigned ltm = (1u << lane) - 1u;
        #pragma unroll
        for (int r = 0; r < Rr; r++) {
            unsigned m = __ballot_sync(0xFFFFFFFFu, (r1 == r) || (r2 == r));
            if (lane == 0) wcnt[w][r] = __popc(m);
            if (r1 == r) rank1 = __popc(m & ltm);
            if (r2 == r) rank2 = __popc(m & ltm);
        }
        __syncthreads();
        int wb1 = 0, wb2 = 0;
        for (int w2i = 0; w2i < w; w2i++) { wb1 += wcnt[w2i][r1]; wb2 += wcnt[w2i][r2]; }

        unsigned short pv = (unsigned short)pix;
        if (r1 == r2) {
            int off = d_segbase[(b * Rr + r1) * 64 + seg] + wb1 + rank1;
            d_list[(b * Rr + r1) * HW + off] = (unsigned short)(pv | (3u << 14));
        } else {
            int off1 = d_segbase[(b * Rr + r1) * 64 + seg] + wb1 + rank1;
            d_list[(b * Rr + r1) * HW + off1] = (unsigned short)(pv | (1u << 14));
            int off2 = d_segbase[(b * Rr + r2) * 64 + seg] + wb2 + rank2;
            d_list[(b * Rr + r2) * HW + off2] = (unsigned short)(pv | (2u << 14));
        }
    }
}

// ================= L4: dynconv via mma.sync, vectorized staging =================
#define DA_BYTES 16384
#define DB_BYTES 20480
#define D_SMEM (2 * DA_BYTES + 2 * DB_BYTES + 1024)   // 74752

__global__ void __launch_bounds__(256) dynconv_mma_kernel() {
    int b = blockIdx.z, r = blockIdx.y;
    int cnt = d_cnt[b * Rr + r];
    int base = blockIdx.x * 128;
    if (base >= cnt) return;

    extern __shared__ __align__(16) char sm[];
    char* Ah = sm;
    char* Al = sm + DA_BYTES;
    char* Bh = sm + 2 * DA_BYTES;
    char* Bl = sm + 2 * DA_BYTES + DB_BYTES;
    int* s_pix = (int*)(sm + 2 * DA_BYTES + 2 * DB_BYTES);
    int* s_fl  = s_pix + 128;
    uint32_t AhA = smem_u32(Ah), AlA = smem_u32(Al);
    uint32_t BhA = smem_u32(Bh), BlA = smem_u32(Bl);

    int tid = threadIdx.x, wid = tid >> 5, l = tid & 31;

    // ---- meta ----
    const unsigned short* lst = d_list + (b * Rr + r) * HW;
    if (tid < 128) {
        int e = base + tid;
        int ent = (e < cnt) ? (int)lst[e] : 0;
        s_fl[tid] = (e < cnt) ? (ent >> 14) : 0;
        s_pix[tid] = ent & 0x3FFF;
    }

    // ---- B copy: precomputed bf16 pairs -> swizzled smem (uint4) ----
    {
        const uint4* kbh = (const uint4*)d_kbh + (size_t)(b * Rr + r) * 1280;
        const uint4* kbl = (const uint4*)d_kbl + (size_t)(b * Rr + r) * 1280;
        #pragma unroll
        for (int ii = 0; ii < 5; ii++) {
            int i = ii * 256 + tid;
            int u = i & 7, cn = i >> 3;
            int n = cn & 31, ck = cn >> 5;
            uint32_t off = ck * 4096 + n * 128 + ((u ^ (n & 7)) << 4);
            *(uint4*)(Bh + off) = __ldg(kbh + i);
            *(uint4*)(Bl + off) = __ldg(kbl + i);
        }
    }
    __syncthreads();

    // ---- hoisted per-thread staging metas ----
    int eb = (tid & 127) >> 2;         // entry sub-index 0..31
    int ui = tid & 3;                  // 16B unit within 64B channel row
    int prec = tid >> 7;               // 0 = hi, 1 = lo
    const unsigned short* ibase = (prec ? d_ibl : d_ibh) + (size_t)b * HW * 32;
    char* Adst = prec ? Al : Ah;
    int pj[4], fj[4], yj[4], xj[4];
    #pragma unroll
    for (int j = 0; j < 4; j++) {
        int e = eb + j * 32;
        pj[j] = s_pix[e]; fj[j] = s_fl[e];
        yj[j] = pj[j] >> 7; xj[j] = pj[j] & 127;
    }

    float acc[4][4];
    #pragma unroll
    for (int nt = 0; nt < 4; nt++)
        #pragma unroll
        for (int i = 0; i < 4; i++) acc[nt][i] = 0.f;

    int rra = wid * 16 + (l & 15);
    int kha = l >> 4;
    int nn = ((l >> 4) & 1) * 8 + (l & 7);
    int khb = (l >> 3) & 1;

    #pragma unroll
    for (int chunk = 0; chunk < 5; chunk++) {
        // ---- stage A (vectorized): tap pair of this chunk ----
        #pragma unroll
        for (int tp = 0; tp < 2; tp++) {
            const int tap = chunk * 2 + tp;
            if (tap < 9) {
                const int ky = tap / 3, kx = tap % 3;
                const int doff = (ky - 1) * Ww + (kx - 1);
                #pragma unroll
                for (int j = 0; j < 4; j++) {
                    int e = eb + j * 32;
                    bool tv = fj[j] && ((unsigned)(yj[j] + ky - 1) < 128u) &&
                              ((unsigned)(xj[j] + kx - 1) < 128u);
                    uint4 v = make_uint4(0u, 0u, 0u, 0u);
                    if (tv)
                        v = __ldg((const uint4*)(ibase + (size_t)(pj[j] + doff) * 32) + ui);
                    int u = tp * 4 + ui;
                    *(uint4*)(Adst + e * 128 + ((u ^ (e & 7)) << 4)) = v;
                }
            }
        }
        __syncthreads();

        // ---- mma over this chunk (k64 = 4 ksteps), 3-product bf16 ----
        #pragma unroll
        for (int kc = 0; kc < 4; kc++) {
            uint32_t ua = (uint32_t)(kc * 2 + kha);
            uint32_t aoff = rra * 128 + ((ua ^ (rra & 7)) << 4);
            uint32_t ah0, ah1, ah2, ah3, al0, al1, al2, al3;
            LDSM4(ah0, ah1, ah2, ah3, AhA + aoff);
            LDSM4(al0, al1, al2, al3, AlA + aoff);

            uint32_t ub = (uint32_t)(kc * 2 + khb);
            uint32_t boff1 = chunk * 4096 + nn * 128 + ((ub ^ (nn & 7)) << 4);
            uint32_t boff2 = chunk * 4096 + (nn + 16) * 128 + ((ub ^ ((nn + 16) & 7)) << 4);
            uint32_t bh0, bh1, bh2, bh3, bh4, bh5, bh6, bh7;
            uint32_t bl0, bl1, bl2, bl3, bl4, bl5, bl6, bl7;
            LDSM4(bh0, bh1, bh2, bh3, BhA + boff1);
            LDSM4(bh4, bh5, bh6, bh7, BhA + boff2);
            LDSM4(bl0, bl1, bl2, bl3, BlA + boff1);
            LDSM4(bl4, bl5, bl6, bl7, BlA + boff2);

            MMA16816(acc[0], ah0, ah1, ah2, ah3, bh0, bh1);
            MMA16816(acc[1], ah0, ah1, ah2, ah3, bh2, bh3);
            MMA16816(acc[2], ah0, ah1, ah2, ah3, bh4, bh5);
            MMA16816(acc[3], ah0, ah1, ah2, ah3, bh6, bh7);
            MMA16816(acc[0], ah0, ah1, ah2, ah3, bl0, bl1);
            MMA16816(acc[1], ah0, ah1, ah2, ah3, bl2, bl3);
            MMA16816(acc[2], ah0, ah1, ah2, ah3, bl4, bl5);
            MMA16816(acc[3], ah0, ah1, ah2, ah3, bl6, bl7);
            MMA16816(acc[0], al0, al1, al2, al3, bh0, bh1);
            MMA16816(acc[1], al0, al1, al2, al3, bh2, bh3);
            MMA16816(acc[2], al0, al1, al2, al3, bh4, bh5);
            MMA16816(acc[3], al0, al1, al2, al3, bh6, bh7);
        }
        __syncthreads();
    }

    // ---- epilogue: D frags -> d_cat[pix][ch], gated by flags ----
    int g = l >> 2, tq = l & 3;
    float* catb = d_cat + (size_t)b * HW * 64;
    #pragma unroll
    for (int rr2 = 0; rr2 < 2; rr2++) {
        int er = wid * 16 + g + rr2 * 8;
        int p = s_pix[er], f = s_fl[er];
        float* cp0 = catb + (size_t)p * 64 + tq * 2;
        #pragma unroll
        for (int nt = 0; nt < 4; nt++) {
            float2 v = make_float2(acc[nt][rr2 * 2], acc[nt][rr2 * 2 + 1]);
            if (f & 1) *(float2*)(cp0 + nt * 8) = v;
            if (f & 2) *(float2*)(cp0 + 32 + nt * 8) = v;
        }
    }
}

// ================= L5: fusion via mma.sync bf16 (3-product split) — unchanged =================
#define FA_BYTES 16640
#define FB_BYTES 4096
#define F_SMEM (2 * FA_BYTES + 2 * FB_BYTES)   // 41472

__global__ void __launch_bounds__(256) fusion_mma_kernel(
    const float* __restrict__ in, const float* __restrict__ b_f,
    float* __restrict__ out) {
    extern __shared__ __align__(16) char sm[];
    char* Ah = sm;
    char* Al = sm + FA_BYTES;
    char* Bh = sm + 2 * FA_BYTES;
    char* Bl = sm + 2 * FA_BYTES + FB_BYTES;
    uint32_t AhA = smem_u32(Ah), AlA = smem_u32(Al);
    uint32_t BhA = smem_u32(Bh), BlA = smem_u32(Bl);

    int tid = threadIdx.x, wid = tid >> 5, l = tid & 31;
    int g = l >> 2, tq = l & 3;
    int y = blockIdx.x, b = blockIdx.y;
    const float* catb = d_cat + (size_t)b * HW * 64;

    float acc[4][4];
    #pragma unroll
    for (int nt = 0; nt < 4; nt++)
        #pragma unroll
        for (int i = 0; i < 4; i++) acc[nt][i] = 0.f;

    for (int ky = 0; ky < 3; ky++) {
        int yy = y + ky - 1;
        if ((unsigned)yy >= 128u) continue;
        __syncthreads();
        {
            const float4* srcb = (const float4*)(catb + ((size_t)yy * 128 - 1) * 64);
            #pragma unroll
            for (int i = 0; i < 9; i++) {
                int f = i * 256 + tid;
                if (f < 2080) {
                    int rr = f >> 4, c4 = f & 15;
                    int sx = rr - 1;
                    float4 v = make_float4(0.f, 0.f, 0.f, 0.f);
                    if ((unsigned)sx < 128u) v = __ldg(srcb + f);
                    uint32_t hx = prmt7632(__float_as_uint(v.x), __float_as_uint(v.y));
                    uint32_t hz = prmt7632(__float_as_uint(v.z), __float_as_uint(v.w));
                    float lx = v.x - __uint_as_float(__float_as_uint(v.x) & 0xFFFF0000u);
                    float ly = v.y - __uint_as_float(__float_as_uint(v.y) & 0xFFFF0000u);
                    float lz = v.z - __uint_as_float(__float_as_uint(v.z) & 0xFFFF0000u);
                    float lw = v.w - __uint_as_float(__float_as_uint(v.w) & 0xFFFF0000u);
                    __nv_bfloat162 p0 = __floats2bfloat162_rn(lx, ly);
                    __nv_bfloat162 p1 = __floats2bfloat162_rn(lz, lw);
                    uint32_t off = rr * 128 + ((((c4 >> 1)) ^ (rr & 7)) << 4) + (c4 & 1) * 8;
                    *(uint2*)(Ah + off) = make_uint2(hx, hz);
                    *(uint2*)(Al + off) = make_uint2(*(uint32_t*)&p0, *(uint32_t*)&p1);
                }
            }
        }
        for (int kx = 0; kx < 3; kx++) {
            int tap = ky * 3 + kx;
            __syncthreads();
            {
                int oo = tid >> 3, u = tid & 7;
                uint4 sh = ((const uint4*)d_wfbh)[tap * 256 + tid];
                uint4 sl = ((const uint4*)d_wfbl)[tap * 256 + tid];
                uint32_t off = oo * 128 + ((u ^ (oo & 7)) << 4);
                *(uint4*)(Bh + off) = sh;
                *(uint4*)(Bl + off) = sl;
            }
            __syncthreads();

            int rra = wid * 16 + (l & 15) + kx;
            int kha = l >> 4;
            int nn = ((l >> 4) & 1) * 8 + (l & 7);
            int khb = (l >> 3) & 1;

            #pragma unroll
            for (int kc = 0; kc < 4; kc++) {
                uint32_t ua = (uint32_t)(kc * 2 + kha);
                uint32_t aoff = rra * 128 + ((ua ^ (rra & 7)) << 4);
                uint32_t ah0, ah1, ah2, ah3, al0, al1, al2, al3;
                LDSM4(ah0, ah1, ah2, ah3, AhA + aoff);
                LDSM4(al0, al1, al2, al3, AlA + aoff);

                uint32_t ub = (uint32_t)(kc * 2 + khb);
                uint32_t boff1 = nn * 128 + ((ub ^ (nn & 7)) << 4);
                uint32_t boff2 = (nn + 16) * 128 + ((ub ^ ((nn + 16) & 7)) << 4);
                uint32_t bh0, bh1, bh2, bh3, bh4, bh5, bh6, bh7;
                uint32_t bl0, bl1, bl2, bl3, bl4, bl5, bl6, bl7;
                LDSM4(bh0, bh1, bh2, bh3, BhA + boff1);
                LDSM4(bh4, bh5, bh6, bh7, BhA + boff2);
                LDSM4(bl0, bl1, bl2, bl3, BlA + boff1);
                LDSM4(bl4, bl5, bl6, bl7, BlA + boff2);

                MMA16816(acc[0], ah0, ah1, ah2, ah3, bh0, bh1);
                MMA16816(acc[1], ah0, ah1, ah2, ah3, bh2, bh3);
                MMA16816(acc[2], ah0, ah1, ah2, ah3, bh4, bh5);
                MMA16816(acc[3], ah0, ah1, ah2, ah3, bh6, bh7);
                MMA16816(acc[0], ah0, ah1, ah2, ah3, bl0, bl1);
                MMA16816(acc[1], ah0, ah1, ah2, ah3, bl2, bl3);
                MMA16816(acc[2], ah0, ah1, ah2, ah3, bl4, bl5);
                MMA16816(acc[3], ah0, ah1, ah2, ah3, bl6, bl7);
                MMA16816(acc[0], al0, al1, al2, al3, bh0, bh1);
                MMA16816(acc[1], al0, al1, al2, al3, bh2, bh3);
                MMA16816(acc[2], al0, al1, al2, al3, bh4, bh5);
                MMA16816(acc[3], al0, al1, al2, al3, bh6, bh7);
            }
        }
    }

    int px0 = wid * 16 + g;
    size_t rowoff = (size_t)y * Ww;
    #pragma unroll
    for (int nt = 0; nt < 4; nt++) {
        int o0 = nt * 8 + tq * 2;
        float bi0 = __ldg(b_f + o0), bi1 = __ldg(b_f + o0 + 1);
        size_t i00 = ((size_t)(b * OUTC + o0)) * HW + rowoff + px0;
        size_t i01 = ((size_t)(b * OUTC + o0 + 1)) * HW + rowoff + px0;
        out[i00]     = acc[nt][0] + bi0 + __ldg(in + i00);
        out[i01]     = acc[nt][1] + bi1 + __ldg(in + i01);
        out[i00 + 8] = acc[nt][2] + bi0 + __ldg(in + i00 + 8);
        out[i01 + 8] = acc[nt][3] + bi1 + __ldg(in + i01 + 8);
    }
}

// ---------------- launch ----------------
extern "C" void kernel_launch(void* const* d_in, const int* in_sizes, int n_in,
                              void* d_out, int out_size) {
    const float* input  = (const float*)d_in[0];
    const float* guide  = (const float*)d_in[1];
    const float* w1     = (const float*)d_in[2];
    const float* b1     = (const float*)d_in[3];
    const float* w2     = (const float*)d_in[4];
    const float* b2     = (const float*)d_in[5];
    const float* w_spa  = (const float*)d_in[6];
    const float* b_spa  = (const float*)d_in[7];
    const float* w_spec = (const float*)d_in[8];
    const float* b_spec = (const float*)d_in[9];
    const float* w_f    = (const float*)d_in[10];
    const float* b_f    = (const float*)d_in[11];
    float* out = (float*)d_out;

    cudaFuncSetAttribute(dynconv_mma_kernel, cudaFuncAttributeMaxDynamicSharedMemorySize, D_SMEM);

    l1_kernel<<<L1_POOL + L1_S1 + L1_WFT + L1_TRANS, 256>>>(
        input, guide, w_spa, b_spa, w_spec, b_spec, w_f);
    l2_kernel<<<Bb + 1, 256>>>(w1, b1);
    l3_kernel<<<L3_KERN + 1024, 256>>>(w2, b2);
    dynconv_mma_kernel<<<dim3(128, Rr, Bb), 256, D_SMEM>>>();
    fusion_mma_kernel<<<dim3(Hh, Bb), 256, F_SMEM>>>(input, b_f, out);
}